// round 13
// baseline (speedup 1.0000x reference)
#include <cuda_runtime.h>
#include <cuda_fp16.h>
#include <cstdint>
#include <cstddef>

#define T_LEN 4096
#define EMBD  300
#define HID   512
#define KTAG  20
#define START_TAG 18
#define STOP_TAG  19
#define NEGV  (-10000.0f)
#define CHUNK 16
#define NCHUNK (T_LEN / CHUNK)   // 256
#define CLUST 16                 // CTAs per direction (one cluster)

// ---------------- scratch (static device globals; no allocation) ----------------
__device__ float              g_xproj[2][T_LEN][4 * HID];  // 64 MB
__device__ float              g_hs[2][T_LEN][HID];         // 16 MB
__device__ float              g_feats[T_LEN][KTAG];
__device__ __align__(16) unsigned long long g_hpair[2][2][HID]; // fallback path only
__device__ float              g_tree[2][NCHUNK][KTAG][KTAG];

__device__ __forceinline__ unsigned long long packhf(unsigned tag, float v) {
    return ((unsigned long long)tag << 32) | (unsigned long long)__float_as_uint(v);
}
__device__ __forceinline__ float tanh_ap(float x) {
    float y;
    asm("tanh.approx.f32 %0, %1;" : "=f"(y) : "f"(x));
    return y;
}
__device__ __forceinline__ float sigm_ap(float x) {
    return fmaf(0.5f, tanh_ap(0.5f * x), 0.5f);
}
__device__ __forceinline__ uint32_t smem_u32(const void* p) {
    uint32_t a;
    asm("{ .reg .u64 t; cvta.to.shared.u64 t, %1; cvt.u32.u64 %0, t; }"
        : "=r"(a) : "l"(p));
    return a;
}

#define MBAR_INIT(addr, cnt) \
    asm volatile("mbarrier.init.shared.b64 [%0], %1;" :: "r"(addr), "r"(cnt) : "memory")
#define MBAR_EXPECT(addr, tx) \
    asm volatile("mbarrier.arrive.expect_tx.shared.b64 _, [%0], %1;" :: "r"(addr), "r"(tx) : "memory")
#define MBAR_WAIT(addr, par) do {                                              \
    uint32_t _m = (addr); uint32_t _p = (par); uint32_t _d;                    \
    asm volatile("{\n\t.reg .pred p;\n\t"                                      \
        "mbarrier.try_wait.parity.acquire.cta.shared::cta.b64 p, [%1], %2;\n\t"\
        "selp.b32 %0, 1, 0, p;\n\t}"                                           \
        : "=r"(_d) : "r"(_m), "r"(_p) : "memory");                             \
    if (!_d) {                                                                 \
        asm volatile("{\n\t.reg .pred P1;\n\t"                                 \
            "WL_%=:\n\t"                                                       \
            "mbarrier.try_wait.parity.acquire.cta.shared::cta.b64 P1, [%0], %1, 0x989680;\n\t" \
            "@P1 bra.uni WD_%=;\n\t"                                           \
            "bra.uni WL_%=;\n\t"                                               \
            "WD_%=:\n\t}"                                                      \
            :: "r"(_m), "r"(_p) : "memory");                                   \
    }                                                                          \
} while (0)
#define CLUSTER_SYNC_ALL() do {                                                \
    asm volatile("barrier.cluster.arrive.aligned;" ::: "memory");              \
    asm volatile("barrier.cluster.wait.aligned;" ::: "memory");                \
} while (0)

// ---------------- init (fallback path): seed h0 pairs ----------------
__global__ void init_kernel(const float* __restrict__ h0) {
    int tid = threadIdx.x;                // 1024 threads
    int dir = tid >> 9, i = tid & 511;
    g_hpair[dir][0][i] = packhf(0u, h0[dir * HID + i]);
    g_hpair[dir][1][i] = packhf(0u, 0.f);
}

__global__ void dummy_kernel() {}

// ---------------- K1: x_proj = emb(gather) @ w_ih^T + b_ih + b_hh ----------------
__global__ __launch_bounds__(256) void xproj_kernel(
    const int*   __restrict__ sentence,
    const float* __restrict__ embed,
    const float* __restrict__ w_ih_f, const float* __restrict__ b_ih_f, const float* __restrict__ b_hh_f,
    const float* __restrict__ w_ih_b, const float* __restrict__ b_ih_b, const float* __restrict__ b_hh_b)
{
    const int dir = blockIdx.z;
    const float* __restrict__ w_ih = dir ? w_ih_b : w_ih_f;
    const float* __restrict__ bi   = dir ? b_ih_b : b_ih_f;
    const float* __restrict__ bh   = dir ? b_hh_b : b_hh_f;

    const int j0 = blockIdx.x * 64;
    const int t0 = blockIdx.y * 64;

    __shared__ __align__(16) float As[8][64];
    __shared__ __align__(16) float Bs[8][64];
    __shared__ int sidx[64];

    const int tid = threadIdx.x;
    if (tid < 64) {
        int t = t0 + tid;
        sidx[tid] = sentence[dir ? (T_LEN - 1 - t) : t];
    }
    __syncthreads();

    const int tx = tid & 15, ty = tid >> 4;
    const int lr = tid >> 2;
    const int le = (tid & 3) * 2;

    float acc[4][4] = {};

    for (int e0 = 0; e0 < EMBD; e0 += 8) {
        const float* arow = embed + (size_t)sidx[lr] * EMBD;
        const float* brow = w_ih + (size_t)(j0 + lr) * EMBD;
        int e = e0 + le;
        As[le][lr]     = (e     < EMBD) ? arow[e]     : 0.f;
        As[le + 1][lr] = (e + 1 < EMBD) ? arow[e + 1] : 0.f;
        Bs[le][lr]     = (e     < EMBD) ? brow[e]     : 0.f;
        Bs[le + 1][lr] = (e + 1 < EMBD) ? brow[e + 1] : 0.f;
        __syncthreads();
#pragma unroll
        for (int kk = 0; kk < 8; kk++) {
            float4 a = *(const float4*)&As[kk][ty * 4];
            float4 b = *(const float4*)&Bs[kk][tx * 4];
            float av[4] = {a.x, a.y, a.z, a.w};
            float bv[4] = {b.x, b.y, b.z, b.w};
#pragma unroll
            for (int i = 0; i < 4; i++)
#pragma unroll
                for (int j = 0; j < 4; j++)
                    acc[i][j] = fmaf(av[i], bv[j], acc[i][j]);
        }
        __syncthreads();
    }

#pragma unroll
    for (int i = 0; i < 4; i++) {
        int t = t0 + ty * 4 + i;
#pragma unroll
        for (int j = 0; j < 4; j++) {
            int jj = j0 + tx * 4 + j;
            g_xproj[dir][t][jj] = acc[i][j] + bi[jj] + bh[jj];
        }
    }
}

// ---------------- K3a: cluster BiLSTM — DSMEM all-gather, fp16 weights ----------------
// Grid 32 CTAs x 512 thr; cluster (16,1,1): cluster 0 = dir 0, cluster 1 = dir 1.
// CTA crank owns h [32*crank, 32*crank+32). Warp w: h0i = crank*32+2w.
// Lane: rowj = lane>>2 (gate rowj&3, h-off rowj>>2), kslice = lane&3 (128 k).
__global__ __launch_bounds__(512, 1) void lstm_cluster_kernel(
    const float* __restrict__ w_hh_f,
    const float* __restrict__ w_hh_b,
    const float* __restrict__ c0,
    const float* __restrict__ h0g)
{
    const int bid   = blockIdx.x;
    const int dir   = bid >> 4;
    const int crank = bid & 15;
    const float* __restrict__ w_hh = dir ? w_hh_b : w_hh_f;

    const int tid  = threadIdx.x;
    const int wid  = tid >> 5;
    const int lane = tid & 31;
    const int h0i  = crank * 32 + 2 * wid;
    const int rowj = lane >> 2;
    const int ksl  = lane & 3;
    const int gate = rowj & 3;
    const int grow = gate * HID + h0i + (rowj >> 2);

    // fp16 weights: this lane's 128 k-values of its row
    __half2 wreg[64];
    {
        const float* wr = w_hh + (size_t)grow * HID + ksl * 128;
#pragma unroll
        for (int i = 0; i < 32; i++) {
            float4 w = *(const float4*)(wr + 4 * i);
            wreg[2 * i]     = __floats2half2_rn(w.x, w.y);
            wreg[2 * i + 1] = __floats2half2_rn(w.z, w.w);
        }
    }

    __shared__ __align__(16) float   hbuf[2][HID];       // fp32 receive buffers
    __shared__ __align__(16) __half2 hh[2][HID / 2];     // converted h
    __shared__ __align__(16) float   stage[2][32];       // CTA fragment staging
    __shared__ __align__(8)  unsigned long long bar[2];

    const uint32_t barA[2]  = { smem_u32(&bar[0]), smem_u32(&bar[1]) };
    const uint32_t hbufA[2] = { smem_u32(&hbuf[0][0]), smem_u32(&hbuf[1][0]) };
    const uint32_t stgA[2]  = { smem_u32(&stage[0][0]), smem_u32(&stage[1][0]) };

    if (tid < HID) hbuf[0][tid] = h0g[dir * HID + tid];
    if (tid == 0) { MBAR_INIT(barA[0], 1); MBAR_INIT(barA[1], 1); }
    __syncthreads();
    CLUSTER_SYNC_ALL();
    if (tid == 0) {                       // expects for h(1) and h(2)
        MBAR_EXPECT(barA[1], CLUST * 128);
        MBAR_EXPECT(barA[0], CLUST * 128);
    }

    float creg = 0.f;
    if (lane == 0)  creg = c0[dir * HID + h0i];
    if (lane == 16) creg = c0[dir * HID + h0i + 1];
    float xp = g_xproj[dir][0][grow];

    int ph[2] = {0, 0};
    for (int t = 0; t < T_LEN; t++) {
        const int b = t & 1;
        if (t > 0) {
            MBAR_WAIT(barA[b], ph[b]);
            ph[b] ^= 1;
            if (tid == 0 && t + 2 < T_LEN) MBAR_EXPECT(barA[b], CLUST * 128);
        }
        // convert received fp32 h(t) to half2
        if (tid < 256)
            hh[b][tid] = __floats2half2_rn(hbuf[b][2 * tid], hbuf[b][2 * tid + 1]);
        __syncthreads();

        // --- matvec: 128 k-values (64 half2) for this lane's row ---
        const __half2* hbase = hh[b] + ksl * 64;
        __half2 a0 = __floats2half2_rn(0.f, 0.f), a1 = a0, a2 = a0, a3 = a0;
#pragma unroll
        for (int c = 0; c < 4; c++) {
            uint4 q0 = *(const uint4*)(hbase + c * 16);
            uint4 q1 = *(const uint4*)(hbase + c * 16 + 4);
            uint4 q2 = *(const uint4*)(hbase + c * 16 + 8);
            uint4 q3 = *(const uint4*)(hbase + c * 16 + 12);
            const __half2* h0p = (const __half2*)&q0;
            const __half2* h1p = (const __half2*)&q1;
            const __half2* h2p = (const __half2*)&q2;
            const __half2* h3p = (const __half2*)&q3;
#pragma unroll
            for (int i = 0; i < 4; i++) {
                a0 = __hfma2(wreg[c * 16 + i],      h0p[i], a0);
                a1 = __hfma2(wreg[c * 16 + 4 + i],  h1p[i], a1);
                a2 = __hfma2(wreg[c * 16 + 8 + i],  h2p[i], a2);
                a3 = __hfma2(wreg[c * 16 + 12 + i], h3p[i], a3);
            }
        }
        __half2 acc = __hadd2(__hadd2(a0, a1), __hadd2(a2, a3));
        // reduce over kslice (lane bits 0,1)
        {
            unsigned u = __shfl_xor_sync(0xffffffffu, *(unsigned*)&acc, 1);
            acc = __hadd2(acc, *(__half2*)&u);
            u = __shfl_xor_sync(0xffffffffu, *(unsigned*)&acc, 2);
            acc = __hadd2(acc, *(__half2*)&u);
        }
        float v = __low2float(acc) + __high2float(acc) + xp;
        float nl = (gate == 2) ? tanh_ap(v) : sigm_ap(v);

        const int base = lane & 16;       // h-select: rows 0-3 lanes 0-15, rows 4-7 lanes 16-31
        float fi = __shfl_sync(0xffffffffu, nl, base + 0);
        float ff = __shfl_sync(0xffffffffu, nl, base + 4);
        float tg = __shfl_sync(0xffffffffu, nl, base + 8);
        float fo = __shfl_sync(0xffffffffu, nl, base + 12);

        float hn = 0.f;
        if ((lane & 15) == 0) {           // lanes 0 (hA) and 16 (hB)
            creg = ff * creg + fi * tg;
            hn = fo * tanh_ap(creg);
        }
        float hnB = __shfl_sync(0xffffffffu, hn, 16);
        if (lane == 0) {
            *(float2*)&stage[b][2 * wid] = make_float2(hn, hnB);
            *(float2*)&g_hs[dir][t][h0i] = make_float2(hn, hnB);
        }
        if (t + 1 < T_LEN) xp = g_xproj[dir][t + 1][grow];
        __syncthreads();

        // --- publish fragment to all 16 peers (incl. self) via DSMEM bulk copy ---
        if (t + 1 < T_LEN && wid == 0) {
            asm volatile("fence.proxy.async.shared::cta;" ::: "memory");
            if (lane < CLUST) {
                const int nb = (t + 1) & 1;
                uint32_t dstLocal = hbufA[nb] + (uint32_t)crank * 128u;
                uint32_t dst, rbar;
                asm("mapa.shared::cluster.u32 %0, %1, %2;"
                    : "=r"(dst) : "r"(dstLocal), "r"(lane));
                asm("mapa.shared::cluster.u32 %0, %1, %2;"
                    : "=r"(rbar) : "r"(barA[nb]), "r"(lane));
                asm volatile(
                    "cp.async.bulk.shared::cluster.shared::cta.mbarrier::complete_tx::bytes "
                    "[%0], [%1], %2, [%3];"
                    :: "r"(dst), "r"(stgA[b]), "r"(128u), "r"(rbar) : "memory");
            }
        }
    }
    CLUSTER_SYNC_ALL();
}

// ---------------- K3b: FALLBACK BiLSTM (R11 verbatim; used if cluster launch fails) ----
__global__ __launch_bounds__(256, 1) void lstm_fallback_kernel(
    const float* __restrict__ w_hh_f,
    const float* __restrict__ w_hh_b,
    const float* __restrict__ c0)
{
    const int dir  = blockIdx.x >> 5;
    const int cid  = blockIdx.x & 31;
    const float* __restrict__ w_hh = dir ? w_hh_b : w_hh_f;

    const int tid  = threadIdx.x;
    const int wid  = tid >> 5;
    const int lane = tid & 31;
    const int h0i  = cid * 16 + 2 * wid;

    float4 w4[8][4];
#pragma unroll
    for (int j = 0; j < 8; j++) {
        const int row = (j & 3) * HID + h0i + (j >> 2);
        const float* wr = w_hh + (size_t)row * HID + 4 * lane;
#pragma unroll
        for (int q = 0; q < 4; q++)
            w4[j][q] = *(const float4*)(wr + q * 128);
    }

    __shared__ __align__(16) float h_sh[2][HID];

    float creg = (lane == 0) ? c0[dir * HID + h0i]
               : (lane == 4) ? c0[dir * HID + h0i + 1] : 0.f;
    float xp = (lane < 8)
             ? g_xproj[dir][0][(lane & 3) * HID + h0i + (lane >> 2)] : 0.f;

    for (int t = 0; t < T_LEN; t++) {
        const int p = t & 1;
        {
            const unsigned long long* pa = g_hpair[dir][p] + 2 * tid;
            const unsigned wanted = (unsigned)t;
            unsigned long long a, b;
            do {
                asm volatile("ld.relaxed.gpu.global.v2.u64 {%0,%1}, [%2];"
                             : "=l"(a), "=l"(b) : "l"(pa) : "memory");
            } while ((unsigned)(a >> 32) < wanted || (unsigned)(b >> 32) < wanted);
            h_sh[p][2 * tid]     = __uint_as_float((unsigned)a);
            h_sh[p][2 * tid + 1] = __uint_as_float((unsigned)b);
        }
        __syncthreads();

        const float* hb = h_sh[p] + 4 * lane;
        float4 hq[4];
#pragma unroll
        for (int q = 0; q < 4; q++) hq[q] = *(const float4*)(hb + q * 128);

        float accv[8];
#pragma unroll
        for (int j = 0; j < 8; j++) {
            float s0 = 0.f, s1 = 0.f;
#pragma unroll
            for (int q = 0; q < 4; q++) {
                s0 = fmaf(w4[j][q].x, hq[q].x, s0);
                s1 = fmaf(w4[j][q].y, hq[q].y, s1);
                s0 = fmaf(w4[j][q].z, hq[q].z, s0);
                s1 = fmaf(w4[j][q].w, hq[q].w, s1);
            }
            accv[j] = s0 + s1;
        }
#pragma unroll
        for (int off = 16; off; off >>= 1) {
#pragma unroll
            for (int j = 0; j < 8; j++)
                accv[j] += __shfl_xor_sync(0xffffffffu, accv[j], off);
        }

        float v = accv[0];
#pragma unroll
        for (int j = 1; j < 8; j++) v = (lane == j) ? accv[j] : v;
        v += xp;
        float nl = ((lane & 3) == 2) ? tanh_ap(v) : sigm_ap(v);

        const int base = lane & 4;
        float ff = __shfl_sync(0xffffffffu, nl, base + 1);
        float tg = __shfl_sync(0xffffffffu, nl, base + 2);
        float fo = __shfl_sync(0xffffffffu, nl, base + 3);

        float hn = 0.f;
        if (lane == 0 || lane == 4) {
            creg = ff * creg + nl * tg;
            hn = fo * tanh_ap(creg);
        }
        float hn1 = __shfl_sync(0xffffffffu, hn, 4);
        if (lane == 0) {
            unsigned tg1 = (unsigned)(t + 1);
            unsigned long long pv0 = packhf(tg1, hn);
            unsigned long long pv1 = packhf(tg1, hn1);
            asm volatile("st.relaxed.gpu.global.v2.u64 [%0], {%1,%2};"
                         :: "l"(g_hpair[dir][p ^ 1] + h0i), "l"(pv0), "l"(pv1)
                         : "memory");
            *(float2*)&g_hs[dir][t][h0i] = make_float2(hn, hn1);
        }
        if (lane < 8 && t + 1 < T_LEN)
            xp = g_xproj[dir][t + 1][(lane & 3) * HID + h0i + (lane >> 2)];
    }
}

// ---------------- K4: feats[t,k] = [h_f(t), h_b(t)] . W_tag[k] + b_tag[k] ----------------
__global__ __launch_bounds__(256) void feats_kernel(
    const float* __restrict__ W_tag, const float* __restrict__ b_tag)
{
    const int t = blockIdx.x;
    __shared__ float hsm[2 * HID];
    const int tid = threadIdx.x;
    for (int i = tid; i < HID; i += 256) {
        hsm[i]       = g_hs[0][t][i];
        hsm[HID + i] = g_hs[1][T_LEN - 1 - t][i];
    }
    __syncthreads();
    const int wid = tid >> 5, lane = tid & 31;
    for (int k = wid; k < KTAG; k += 8) {
        const float* wrow = W_tag + (size_t)k * (2 * HID);
        float s = 0.f;
#pragma unroll
        for (int m = 0; m < 32; m++)
            s = fmaf(wrow[m * 32 + lane], hsm[m * 32 + lane], s);
#pragma unroll
        for (int off = 16; off; off >>= 1)
            s += __shfl_xor_sync(0xffffffffu, s, off);
        if (lane == 0) g_feats[t][k] = s + b_tag[k];
    }
}

// ---------------- K5a: per-chunk sequential composition ----------------
__global__ __launch_bounds__(32) void crf_chunk_kernel(const float* __restrict__ trans)
{
    const int c = blockIdx.x;
    const int lane = threadIdx.x;
    __shared__ float Tsm[KTAG][KTAG];
    __shared__ float Mbuf[2][KTAG][KTAG];
    __shared__ float fsm[KTAG];

    for (int i = lane; i < KTAG * KTAG; i += 32)
        Tsm[i / KTAG][i % KTAG] = trans[i];
    __syncwarp();

    if (lane < KTAG) fsm[lane] = g_feats[c * CHUNK][lane];
    __syncwarp();
    for (int e = lane; e < KTAG * KTAG; e += 32)
        Mbuf[0][e / KTAG][e % KTAG] = Tsm[e / KTAG][e % KTAG] + fsm[e / KTAG];
    __syncwarp();

    int cur = 0;
    for (int s = 1; s < CHUNK; s++) {
        if (lane < KTAG) fsm[lane] = g_feats[c * CHUNK + s][lane];
        __syncwarp();
        for (int e = lane; e < KTAG * KTAG; e += 32) {
            int j = e / KTAG, i = e % KTAG;
            float v[KTAG], mx = -3.4e38f;
#pragma unroll
            for (int k = 0; k < KTAG; k++) {
                v[k] = Tsm[j][k] + Mbuf[cur][k][i];
                mx = fmaxf(mx, v[k]);
            }
            float sm = 0.f;
#pragma unroll
            for (int k = 0; k < KTAG; k++) sm += __expf(v[k] - mx);
            Mbuf[cur ^ 1][j][i] = fsm[j] + mx + __logf(sm);
        }
        __syncwarp();
        cur ^= 1;
    }
    for (int e = lane; e < KTAG * KTAG; e += 32)
        g_tree[0][c][e / KTAG][e % KTAG] = Mbuf[cur][e / KTAG][e % KTAG];
}

// ---------------- K5b: tree combine ----------------
__global__ __launch_bounds__(32) void crf_combine_kernel(int s)
{
    const int b = blockIdx.x;
    const int lane = threadIdx.x;
    const float (*in)[KTAG][KTAG]  = g_tree[s & 1];
    float (*out)[KTAG][KTAG]       = g_tree[(s & 1) ^ 1];
    __shared__ float Lo[KTAG][KTAG], Hi[KTAG][KTAG];
    for (int i = lane; i < KTAG * KTAG; i += 32) {
        Lo[i / KTAG][i % KTAG] = in[2 * b][i / KTAG][i % KTAG];
        Hi[i / KTAG][i % KTAG] = in[2 * b + 1][i / KTAG][i % KTAG];
    }
    __syncwarp();
    for (int e = lane; e < KTAG * KTAG; e += 32) {
        int j = e / KTAG, i = e % KTAG;
        float v[KTAG], mx = -3.4e38f;
#pragma unroll
        for (int k = 0; k < KTAG; k++) {
            v[k] = Hi[j][k] + Lo[k][i];
            mx = fmaxf(mx, v[k]);
        }
        float sm = 0.f;
#pragma unroll
        for (int k = 0; k < KTAG; k++) sm += __expf(v[k] - mx);
        out[b][j][i] = mx + __logf(sm);
    }
}

// ---------------- K5c: final score ----------------
__global__ void crf_final_kernel(const int* __restrict__ tags,
                                 const float* __restrict__ trans,
                                 float* __restrict__ out)
{
    __shared__ float partial[128];
    const int tid = threadIdx.x;

    float loc = 0.f;
    for (int t = tid; t < T_LEN; t += 128) {
        int tg = tags[t];
        int pv = t ? tags[t - 1] : START_TAG;
        loc += trans[tg * KTAG + pv] + g_feats[t][tg];
    }
    partial[tid] = loc;
    __syncthreads();

    if (tid == 0) {
        float gold = trans[STOP_TAG * KTAG + tags[T_LEN - 1]];
        for (int i = 0; i < 128; i++) gold += partial[i];

        const float (*C)[KTAG] = g_tree[0][0];
        float alpha[KTAG];
        for (int j = 0; j < KTAG; j++) {
            float mx = -3.4e38f, v[KTAG];
            for (int i = 0; i < KTAG; i++) {
                v[i] = C[j][i] + ((i == START_TAG) ? 0.f : NEGV);
                mx = fmaxf(mx, v[i]);
            }
            float sm = 0.f;
            for (int i = 0; i < KTAG; i++) sm += __expf(v[i] - mx);
            alpha[j] = mx + __logf(sm);
        }
        float mx = -3.4e38f;
        for (int j = 0; j < KTAG; j++)
            mx = fmaxf(mx, alpha[j] + trans[STOP_TAG * KTAG + j]);
        float sm = 0.f;
        for (int j = 0; j < KTAG; j++)
            sm += __expf(alpha[j] + trans[STOP_TAG * KTAG + j] - mx);
        out[0] = (mx + __logf(sm)) - gold;
    }
}

// ---------------- launch ----------------
extern "C" void kernel_launch(void* const* d_in, const int* in_sizes, int n_in,
                              void* d_out, int out_size)
{
    const int*   sentence = (const int*)d_in[0];
    const int*   tags     = (const int*)d_in[1];
    const float* embed    = (const float*)d_in[2];
    const float* w_ih_f   = (const float*)d_in[3];
    const float* w_hh_f   = (const float*)d_in[4];
    const float* b_ih_f   = (const float*)d_in[5];
    const float* b_hh_f   = (const float*)d_in[6];
    const float* w_ih_b   = (const float*)d_in[7];
    const float* w_hh_b   = (const float*)d_in[8];
    const float* b_ih_b   = (const float*)d_in[9];
    const float* b_hh_b   = (const float*)d_in[10];
    const float* h0       = (const float*)d_in[11];
    const float* c0       = (const float*)d_in[12];
    const float* W_tag    = (const float*)d_in[13];
    const float* b_tag    = (const float*)d_in[14];
    const float* trans    = (const float*)d_in[15];

    dim3 g1((4 * HID) / 64, T_LEN / 64, 2);
    xproj_kernel<<<g1, 256>>>(sentence, embed,
                              w_ih_f, b_ih_f, b_hh_f,
                              w_ih_b, b_ih_b, b_hh_b);

    dummy_kernel<<<1, 32>>>();   // ncu -s 5 window: pre,pre,xproj,dummy,dummy -> lstm
    dummy_kernel<<<1, 32>>>();

    // cluster launch: 2 clusters of 16 CTAs (nonportable size)
    cudaFuncSetAttribute(lstm_cluster_kernel,
                         cudaFuncAttributeNonPortableClusterSizeAllowed, 1);
    cudaLaunchConfig_t cfg = {};
    cfg.gridDim = dim3(2 * CLUST, 1, 1);
    cfg.blockDim = dim3(512, 1, 1);
    cfg.dynamicSmemBytes = 0;
    cfg.stream = (cudaStream_t)0;
    cudaLaunchAttribute attrs[1];
    attrs[0].id = cudaLaunchAttributeClusterDimension;
    attrs[0].val.clusterDim.x = CLUST;
    attrs[0].val.clusterDim.y = 1;
    attrs[0].val.clusterDim.z = 1;
    cfg.attrs = attrs;
    cfg.numAttrs = 1;

    cudaError_t err = cudaLaunchKernelEx(&cfg, lstm_cluster_kernel,
                                         w_hh_f, w_hh_b, c0, h0);
    if (err != cudaSuccess) {
        cudaGetLastError();              // clear sticky error; take fallback path
        init_kernel<<<1, 1024>>>(h0);
        lstm_fallback_kernel<<<64, 256>>>(w_hh_f, w_hh_b, c0);
    }

    feats_kernel<<<T_LEN, 256>>>(W_tag, b_tag);

    crf_chunk_kernel<<<NCHUNK, 32>>>(trans);
    for (int s = 0; s < 8; s++)
        crf_combine_kernel<<<(NCHUNK / 2) >> s, 32>>>(s);
    crf_final_kernel<<<1, 128>>>(tags, trans, (float*)d_out);
}

// round 16
// speedup vs baseline: 2.1820x; 2.1820x over previous
#include <cuda_runtime.h>
#include <cuda_fp16.h>
#include <cstdint>
#include <cstddef>

#define T_LEN 4096
#define EMBD  300
#define HID   512
#define KTAG  20
#define START_TAG 18
#define STOP_TAG  19
#define NEGV  (-10000.0f)
#define CHUNK 16
#define NCHUNK (T_LEN / CHUNK)   // 256
#define TSPLIT 768               // rows < TSPLIT precomputed; rest by worker CTAs
#define NWORK  84                // worker CTAs inside the fused launch
#define TILES_T ((T_LEN - TSPLIT) / 64)   // 52
#define NTILES (32 * TILES_T * 2)         // 3328

// ---------------- scratch (static device globals; no allocation) ----------------
__device__ float              g_xproj[2][T_LEN][4 * HID];  // 64 MB
__device__ float              g_hs[2][T_LEN][HID];         // 16 MB
__device__ float              g_feats[T_LEN][KTAG];
__device__ __align__(16) unsigned long long g_hpair[2][2][HID]; // [dir][parity][h]: {tag|bits}
__device__ float              g_tree[2][NCHUNK][KTAG][KTAG];
__device__ unsigned           g_xready;

__device__ __forceinline__ unsigned long long packhf(unsigned tag, float v) {
    return ((unsigned long long)tag << 32) | (unsigned long long)__float_as_uint(v);
}
__device__ __forceinline__ float tanh_ap(float x) {
    float y;
    asm("tanh.approx.f32 %0, %1;" : "=f"(y) : "f"(x));
    return y;
}
__device__ __forceinline__ float sigm_ap(float x) {
    return fmaf(0.5f, tanh_ap(0.5f * x), 0.5f);
}

// ---------------- init: seed h0 (tag 0); reset worker counter ----------------
__global__ void init_kernel(const float* __restrict__ h0) {
    int tid = threadIdx.x;                // 1024 threads
    int dir = tid >> 9, i = tid & 511;
    g_hpair[dir][0][i] = packhf(0u, h0[dir * HID + i]);
    g_hpair[dir][1][i] = packhf(0u, 0.f);   // tag 0 < first wanted tag (1)
    if (tid == 0) g_xready = 0u;
}

// dummy launch: positions ncu's "-s 5 -c 1" window on the fused lstm kernel
__global__ void dummy_kernel() {}

// ---------------- xproj tile body (shared by K1 and fused workers) ----------------
__device__ __forceinline__ void xproj_tile(
    int dir, int j0, int t0, int tid,
    const int*   __restrict__ sentence,
    const float* __restrict__ embed,
    const float* __restrict__ w_ih, const float* __restrict__ bi, const float* __restrict__ bh,
    float (*As)[64], float (*Bs)[64], int* sidx)
{
    if (tid < 64) {
        int t = t0 + tid;
        sidx[tid] = sentence[dir ? (T_LEN - 1 - t) : t];
    }
    __syncthreads();

    const int tx = tid & 15, ty = tid >> 4;
    const int lr = tid >> 2;
    const int le = (tid & 3) * 2;

    float acc[4][4] = {};

    for (int e0 = 0; e0 < EMBD; e0 += 8) {
        const float* arow = embed + (size_t)sidx[lr] * EMBD;
        const float* brow = w_ih + (size_t)(j0 + lr) * EMBD;
        int e = e0 + le;
        As[le][lr]     = (e     < EMBD) ? arow[e]     : 0.f;
        As[le + 1][lr] = (e + 1 < EMBD) ? arow[e + 1] : 0.f;
        Bs[le][lr]     = (e     < EMBD) ? brow[e]     : 0.f;
        Bs[le + 1][lr] = (e + 1 < EMBD) ? brow[e + 1] : 0.f;
        __syncthreads();
#pragma unroll
        for (int kk = 0; kk < 8; kk++) {
            float4 a = *(const float4*)&As[kk][ty * 4];
            float4 b = *(const float4*)&Bs[kk][tx * 4];
            float av[4] = {a.x, a.y, a.z, a.w};
            float bv[4] = {b.x, b.y, b.z, b.w};
#pragma unroll
            for (int i = 0; i < 4; i++)
#pragma unroll
                for (int j = 0; j < 4; j++)
                    acc[i][j] = fmaf(av[i], bv[j], acc[i][j]);
        }
        __syncthreads();
    }

#pragma unroll
    for (int i = 0; i < 4; i++) {
        int t = t0 + ty * 4 + i;
#pragma unroll
        for (int j = 0; j < 4; j++) {
            int jj = j0 + tx * 4 + j;
            g_xproj[dir][t][jj] = acc[i][j] + bi[jj] + bh[jj];
        }
    }
}

// ---------------- K1: xproj part A (t < TSPLIT) ----------------
__global__ __launch_bounds__(256) void xproj_kernel(
    const int*   __restrict__ sentence,
    const float* __restrict__ embed,
    const float* __restrict__ w_ih_f, const float* __restrict__ b_ih_f, const float* __restrict__ b_hh_f,
    const float* __restrict__ w_ih_b, const float* __restrict__ b_ih_b, const float* __restrict__ b_hh_b)
{
    const int dir = blockIdx.z;
    __shared__ __align__(16) float As[8][64];
    __shared__ __align__(16) float Bs[8][64];
    __shared__ int sidx[64];
    xproj_tile(dir, blockIdx.x * 64, blockIdx.y * 64, threadIdx.x,
               sentence, embed,
               dir ? w_ih_b : w_ih_f, dir ? b_ih_b : b_ih_f, dir ? b_hh_b : b_hh_f,
               As, Bs, sidx);
}

// ---------------- K3: FUSED persistent BiLSTM + xprojB workers ----------------
// 148 CTAs x 256 thr, 1 CTA/SM (regs force occ=1 -> all resident in wave 1).
// CTAs 0..63: R11 lstm (32/dir; warp w owns h0i=cid*16+2w, h0i+1).
// CTAs 64..147: compute xproj tiles for t >= TSPLIT, then bump g_xready.
__global__ __launch_bounds__(256, 1) void lstm_fused_kernel(
    const float* __restrict__ w_hh_f,
    const float* __restrict__ w_hh_b,
    const float* __restrict__ c0,
    const int*   __restrict__ sentence,
    const float* __restrict__ embed,
    const float* __restrict__ w_ih_f, const float* __restrict__ b_ih_f, const float* __restrict__ b_hh_f,
    const float* __restrict__ w_ih_b, const float* __restrict__ b_ih_b, const float* __restrict__ b_hh_b)
{
    const int tid = threadIdx.x;

    if (blockIdx.x >= 64) {
        // ---------------- worker path: xproj tiles for t >= TSPLIT ----------------
        __shared__ __align__(16) float As[8][64];
        __shared__ __align__(16) float Bs[8][64];
        __shared__ int sidx[64];
        const int w = blockIdx.x - 64;
        for (int m = w; m < NTILES; m += NWORK) {
            const int dir = m / (32 * TILES_T);
            const int rem = m % (32 * TILES_T);
            const int t0 = TSPLIT + (rem / 32) * 64;
            const int j0 = (rem % 32) * 64;
            xproj_tile(dir, j0, t0, tid, sentence, embed,
                       dir ? w_ih_b : w_ih_f, dir ? b_ih_b : b_ih_f,
                       dir ? b_hh_b : b_hh_f, As, Bs, sidx);
            __syncthreads();
        }
        __threadfence();
        __syncthreads();
        if (tid == 0) atomicAdd(&g_xready, 1u);
        return;
    }

    // ---------------- lstm path (R11 verbatim + one-time gate) ----------------
    const int dir  = blockIdx.x >> 5;
    const int cid  = blockIdx.x & 31;
    const float* __restrict__ w_hh = dir ? w_hh_b : w_hh_f;

    const int wid  = tid >> 5;
    const int lane = tid & 31;
    const int h0i  = cid * 16 + 2 * wid;

    // weights: 8 rows (j = gate + 4*(h offset)), 16 k-values per lane
    float4 w4[8][4];
#pragma unroll
    for (int j = 0; j < 8; j++) {
        const int row = (j & 3) * HID + h0i + (j >> 2);
        const float* wr = w_hh + (size_t)row * HID + 4 * lane;
#pragma unroll
        for (int q = 0; q < 4; q++)
            w4[j][q] = *(const float4*)(wr + q * 128);
    }

    __shared__ __align__(16) float h_sh[2][HID];

    float creg = (lane == 0) ? c0[dir * HID + h0i]
               : (lane == 4) ? c0[dir * HID + h0i + 1] : 0.f;
    float xp = (lane < 8)
             ? g_xproj[dir][0][(lane & 3) * HID + h0i + (lane >> 2)] : 0.f;

    for (int t = 0; t < T_LEN; t++) {
        // one-time gate: workers must have finished xproj rows >= TSPLIT
        if (t == TSPLIT - 1) {
            if (tid == 0) {
                unsigned r;
                do {
                    asm volatile("ld.acquire.gpu.global.u32 %0, [%1];"
                                 : "=r"(r) : "l"(&g_xready) : "memory");
                } while (r < (unsigned)NWORK);
            }
            __syncthreads();
        }

        const int p = t & 1;
        // --- poll own 2 pairs of h(t), monotone tag check, stash to smem ---
        {
            const unsigned long long* pa = g_hpair[dir][p] + 2 * tid;
            const unsigned wanted = (unsigned)t;
            unsigned long long a, b;
            do {
                asm volatile("ld.relaxed.gpu.global.v2.u64 {%0,%1}, [%2];"
                             : "=l"(a), "=l"(b) : "l"(pa) : "memory");
            } while ((unsigned)(a >> 32) < wanted || (unsigned)(b >> 32) < wanted);
            h_sh[p][2 * tid]     = __uint_as_float((unsigned)a);
            h_sh[p][2 * tid + 1] = __uint_as_float((unsigned)b);
        }
        __syncthreads();

        // --- matvec: 16 h values per lane feed all 8 rows ---
        const float* hb = h_sh[p] + 4 * lane;
        float4 hq[4];
#pragma unroll
        for (int q = 0; q < 4; q++) hq[q] = *(const float4*)(hb + q * 128);

        float accv[8];
#pragma unroll
        for (int j = 0; j < 8; j++) {
            float s0 = 0.f, s1 = 0.f;
#pragma unroll
            for (int q = 0; q < 4; q++) {
                s0 = fmaf(w4[j][q].x, hq[q].x, s0);
                s1 = fmaf(w4[j][q].y, hq[q].y, s1);
                s0 = fmaf(w4[j][q].z, hq[q].z, s0);
                s1 = fmaf(w4[j][q].w, hq[q].w, s1);
            }
            accv[j] = s0 + s1;
        }
#pragma unroll
        for (int off = 16; off; off >>= 1) {
#pragma unroll
            for (int j = 0; j < 8; j++)
                accv[j] += __shfl_xor_sync(0xffffffffu, accv[j], off);
        }

        // lane j (0..7) applies nonlinearity for row j
        float v = accv[0];
#pragma unroll
        for (int j = 1; j < 8; j++) v = (lane == j) ? accv[j] : v;
        v += xp;
        float nl = ((lane & 3) == 2) ? tanh_ap(v) : sigm_ap(v);

        const int base = lane & 4;   // gate group base for lanes 0..7
        float ff = __shfl_sync(0xffffffffu, nl, base + 1);
        float tg = __shfl_sync(0xffffffffu, nl, base + 2);
        float fo = __shfl_sync(0xffffffffu, nl, base + 3);

        // lanes 0 and 4 hold cells for h0i and h0i+1
        float hn = 0.f;
        if (lane == 0 || lane == 4) {
            creg = ff * creg + nl * tg;          // nl = fi on lanes 0,4
            hn = fo * tanh_ap(creg);
        }
        float hn1 = __shfl_sync(0xffffffffu, hn, 4);
        if (lane == 0) {
            unsigned tg1 = (unsigned)(t + 1);
            unsigned long long pv0 = packhf(tg1, hn);
            unsigned long long pv1 = packhf(tg1, hn1);
            asm volatile("st.relaxed.gpu.global.v2.u64 [%0], {%1,%2};"
                         :: "l"(g_hpair[dir][p ^ 1] + h0i), "l"(pv0), "l"(pv1)
                         : "memory");
            *(float2*)&g_hs[dir][t][h0i] = make_float2(hn, hn1);
        }
        if (lane < 8 && t + 1 < T_LEN)
            xp = g_xproj[dir][t + 1][(lane & 3) * HID + h0i + (lane >> 2)];
        // no trailing barrier: next stash targets the other parity buffer.
    }
}

// ---------------- K4: feats[t,k] = [h_f(t), h_b(t)] . W_tag[k] + b_tag[k] ----------------
__global__ __launch_bounds__(256) void feats_kernel(
    const float* __restrict__ W_tag, const float* __restrict__ b_tag)
{
    const int t = blockIdx.x;
    __shared__ float hsm[2 * HID];
    const int tid = threadIdx.x;
    for (int i = tid; i < HID; i += 256) {
        hsm[i]       = g_hs[0][t][i];
        hsm[HID + i] = g_hs[1][T_LEN - 1 - t][i];
    }
    __syncthreads();
    const int wid = tid >> 5, lane = tid & 31;
    for (int k = wid; k < KTAG; k += 8) {
        const float* wrow = W_tag + (size_t)k * (2 * HID);
        float s = 0.f;
#pragma unroll
        for (int m = 0; m < 32; m++)
            s = fmaf(wrow[m * 32 + lane], hsm[m * 32 + lane], s);
#pragma unroll
        for (int off = 16; off; off >>= 1)
            s += __shfl_xor_sync(0xffffffffu, s, off);
        if (lane == 0) g_feats[t][k] = s + b_tag[k];
    }
}

// ---------------- K5a: per-chunk sequential composition (256 warps) ----------------
__global__ __launch_bounds__(32) void crf_chunk_kernel(const float* __restrict__ trans)
{
    const int c = blockIdx.x;
    const int lane = threadIdx.x;
    __shared__ float Tsm[KTAG][KTAG];
    __shared__ float Mbuf[2][KTAG][KTAG];
    __shared__ float fsm[KTAG];

    for (int i = lane; i < KTAG * KTAG; i += 32)
        Tsm[i / KTAG][i % KTAG] = trans[i];
    __syncwarp();

    if (lane < KTAG) fsm[lane] = g_feats[c * CHUNK][lane];
    __syncwarp();
    for (int e = lane; e < KTAG * KTAG; e += 32)
        Mbuf[0][e / KTAG][e % KTAG] = Tsm[e / KTAG][e % KTAG] + fsm[e / KTAG];
    __syncwarp();

    int cur = 0;
    for (int s = 1; s < CHUNK; s++) {
        if (lane < KTAG) fsm[lane] = g_feats[c * CHUNK + s][lane];
        __syncwarp();
        for (int e = lane; e < KTAG * KTAG; e += 32) {
            int j = e / KTAG, i = e % KTAG;
            float v[KTAG], mx = -3.4e38f;
#pragma unroll
            for (int k = 0; k < KTAG; k++) {
                v[k] = Tsm[j][k] + Mbuf[cur][k][i];
                mx = fmaxf(mx, v[k]);
            }
            float sm = 0.f;
#pragma unroll
            for (int k = 0; k < KTAG; k++) sm += __expf(v[k] - mx);
            Mbuf[cur ^ 1][j][i] = fsm[j] + mx + __logf(sm);
        }
        __syncwarp();
        cur ^= 1;
    }
    for (int e = lane; e < KTAG * KTAG; e += 32)
        g_tree[0][c][e / KTAG][e % KTAG] = Mbuf[cur][e / KTAG][e % KTAG];
}

// ---------------- K5b: tree combine. out[b] = in[2b+1] (.) in[2b] ----------------
__global__ __launch_bounds__(32) void crf_combine_kernel(int s)
{
    const int b = blockIdx.x;
    const int lane = threadIdx.x;
    const float (*in)[KTAG][KTAG]  = g_tree[s & 1];
    float (*out)[KTAG][KTAG]       = g_tree[(s & 1) ^ 1];
    __shared__ float Lo[KTAG][KTAG], Hi[KTAG][KTAG];
    for (int i = lane; i < KTAG * KTAG; i += 32) {
        Lo[i / KTAG][i % KTAG] = in[2 * b][i / KTAG][i % KTAG];
        Hi[i / KTAG][i % KTAG] = in[2 * b + 1][i / KTAG][i % KTAG];
    }
    __syncwarp();
    for (int e = lane; e < KTAG * KTAG; e += 32) {
        int j = e / KTAG, i = e % KTAG;
        float v[KTAG], mx = -3.4e38f;
#pragma unroll
        for (int k = 0; k < KTAG; k++) {
            v[k] = Hi[j][k] + Lo[k][i];
            mx = fmaxf(mx, v[k]);
        }
        float sm = 0.f;
#pragma unroll
        for (int k = 0; k < KTAG; k++) sm += __expf(v[k] - mx);
        out[b][j][i] = mx + __logf(sm);
    }
}

// ---------------- K5c: final score = forward - gold ----------------
__global__ void crf_final_kernel(const int* __restrict__ tags,
                                 const float* __restrict__ trans,
                                 float* __restrict__ out)
{
    __shared__ float partial[128];
    const int tid = threadIdx.x;

    float loc = 0.f;
    for (int t = tid; t < T_LEN; t += 128) {
        int tg = tags[t];
        int pv = t ? tags[t - 1] : START_TAG;
        loc += trans[tg * KTAG + pv] + g_feats[t][tg];
    }
    partial[tid] = loc;
    __syncthreads();

    if (tid == 0) {
        float gold = trans[STOP_TAG * KTAG + tags[T_LEN - 1]];
        for (int i = 0; i < 128; i++) gold += partial[i];

        const float (*C)[KTAG] = g_tree[0][0];
        float alpha[KTAG];
        for (int j = 0; j < KTAG; j++) {
            float mx = -3.4e38f, v[KTAG];
            for (int i = 0; i < KTAG; i++) {
                v[i] = C[j][i] + ((i == START_TAG) ? 0.f : NEGV);
                mx = fmaxf(mx, v[i]);
            }
            float sm = 0.f;
            for (int i = 0; i < KTAG; i++) sm += __expf(v[i] - mx);
            alpha[j] = mx + __logf(sm);
        }
        float mx = -3.4e38f;
        for (int j = 0; j < KTAG; j++)
            mx = fmaxf(mx, alpha[j] + trans[STOP_TAG * KTAG + j]);
        float sm = 0.f;
        for (int j = 0; j < KTAG; j++)
            sm += __expf(alpha[j] + trans[STOP_TAG * KTAG + j] - mx);
        out[0] = (mx + __logf(sm)) - gold;
    }
}

// ---------------- launch ----------------
extern "C" void kernel_launch(void* const* d_in, const int* in_sizes, int n_in,
                              void* d_out, int out_size)
{
    const int*   sentence = (const int*)d_in[0];
    const int*   tags     = (const int*)d_in[1];
    const float* embed    = (const float*)d_in[2];
    const float* w_ih_f   = (const float*)d_in[3];
    const float* w_hh_f   = (const float*)d_in[4];
    const float* b_ih_f   = (const float*)d_in[5];
    const float* b_hh_f   = (const float*)d_in[6];
    const float* w_ih_b   = (const float*)d_in[7];
    const float* w_hh_b   = (const float*)d_in[8];
    const float* b_ih_b   = (const float*)d_in[9];
    const float* b_hh_b   = (const float*)d_in[10];
    const float* h0       = (const float*)d_in[11];
    const float* c0       = (const float*)d_in[12];
    const float* W_tag    = (const float*)d_in[13];
    const float* b_tag    = (const float*)d_in[14];
    const float* trans    = (const float*)d_in[15];

    init_kernel<<<1, 1024>>>(h0);

    // xproj part A: t in [0, TSPLIT)
    dim3 gA((4 * HID) / 64, TSPLIT / 64, 2);
    xproj_kernel<<<gA, 256>>>(sentence, embed,
                              w_ih_f, b_ih_f, b_hh_f,
                              w_ih_b, b_ih_b, b_hh_b);

    dummy_kernel<<<1, 32>>>();   // ncu -s 5: pre,pre,init,xprojA,dummy -> fused lstm

    // fused: 64 lstm CTAs + 84 xprojB worker CTAs, all resident (1 CTA/SM)
    lstm_fused_kernel<<<148, 256>>>(w_hh_f, w_hh_b, c0,
                                    sentence, embed,
                                    w_ih_f, b_ih_f, b_hh_f,
                                    w_ih_b, b_ih_b, b_hh_b);

    feats_kernel<<<T_LEN, 256>>>(W_tag, b_tag);

    crf_chunk_kernel<<<NCHUNK, 32>>>(trans);
    for (int s = 0; s < 8; s++)
        crf_combine_kernel<<<(NCHUNK / 2) >> s, 32>>>(s);
    crf_final_kernel<<<1, 128>>>(tags, trans, (float*)d_out);
}